// round 11
// baseline (speedup 1.0000x reference)
#include <cuda_runtime.h>
#include <cstddef>

using ull = unsigned long long;

// Problem constants
constexpr int B_   = 64;
constexpr int T_   = 2048;
constexpr int H_   = 100;
constexpr int IN_  = 10;
constexpr int OUT_ = 10;
constexpr int L_   = 5;
constexpr int M_   = B_ * T_;          // 131072 rows
constexpr int BUF_ELEMS = M_ * H_;     // 52.4 MB

constexpr int TC_    = 64;             // timesteps per chunk
constexpr int NC_    = T_ / TC_;       // 32 chunks
constexpr int NSTAGE = NC_ + L_ - 1;   // 36 wavefront stages

// Scratch (device globals: no allocation anywhere)
__device__ float g_bufA[BUF_ELEMS];            // output of layers 0,2,4
__device__ float g_bufB[BUF_ELEMS];            // output of layers 1,3
__device__ float g_xp0[BUF_ELEMS];             // precomputed layer-0 xp
__device__ float g_xpc[L_ * B_ * TC_ * H_];    // per-stage xp chunks (l>=1)
__device__ float g_hst[L_ * B_ * H_];          // hidden-state carry

// ---------------------------------------------------------------------------
// Packed f32x2 helpers (sm_103a FFMA2/FADD2 via PTX)
// ---------------------------------------------------------------------------
__device__ __forceinline__ ull ffma2(ull a, ull b, ull c) {
    ull d;
    asm("fma.rn.f32x2 %0, %1, %2, %3;" : "=l"(d) : "l"(a), "l"(b), "l"(c));
    return d;
}
__device__ __forceinline__ ull addf2(ull a, ull b) {
    ull d;
    asm("add.rn.f32x2 %0, %1, %2;" : "=l"(d) : "l"(a), "l"(b));
    return d;
}
__device__ __forceinline__ ull pack2(float lo, float hi) {
    ull r;
    asm("mov.b64 %0, {%1, %2};" : "=l"(r) : "f"(lo), "f"(hi));
    return r;
}
__device__ __forceinline__ float lo2(ull v) {
    return __uint_as_float((unsigned)(v & 0xFFFFFFFFull));
}
__device__ __forceinline__ float hi2(ull v) {
    return __uint_as_float((unsigned)(v >> 32));
}

// ---------------------------------------------------------------------------
// Fast, overflow-safe tanh: tanh(x) = sign(x)*(1-e)/(1+e), e = 2^(-2|x|log2e)
// ---------------------------------------------------------------------------
__device__ __forceinline__ float fast_tanh(float x) {
    float t = fabsf(x) * -2.8853900817779268f;   // -2*log2(e)*|x|
    float e;
    asm("ex2.approx.f32 %0, %1;" : "=f"(e) : "f"(t));
    float r = __fdividef(1.0f - e, 1.0f + e);
    return copysignf(r, x);
}

// ---------------------------------------------------------------------------
// Prologue: layer-0 input GEMM over the ENTIRE sequence (depends only on x).
// ---------------------------------------------------------------------------
__global__ void __launch_bounds__(256)
gemm0_k(const float* __restrict__ A, const float* __restrict__ W,
        const float* __restrict__ b1, const float* __restrict__ b2,
        float* __restrict__ C)
{
    __shared__ __align__(16) float Ws[H_ * IN_];
    __shared__ __align__(16) float As[16 * IN_];

    for (int i = threadIdx.x; i < H_ * IN_; i += 256) Ws[i] = W[i];

    const int c = threadIdx.x & 127;
    const int g = threadIdx.x >> 7;
    const bool act = (c < H_);
    const float bias = act ? (b1[c] + b2[c]) : 0.0f;

    const int tilesTotal = M_ / 16;
    for (int tile = blockIdx.x; tile < tilesTotal; tile += gridDim.x) {
        __syncthreads();
        const float* Arow = A + (size_t)tile * 16 * IN_;
        for (int i = threadIdx.x; i < 16 * IN_; i += 256) As[i] = Arow[i];
        __syncthreads();

        if (act) {
            float acc[8];
            #pragma unroll
            for (int r = 0; r < 8; r++) acc[r] = bias;
            #pragma unroll
            for (int k = 0; k < IN_; k++) {
                const float wv = Ws[c * IN_ + k];
                #pragma unroll
                for (int r = 0; r < 8; r++)
                    acc[r] += wv * As[(g + 2 * r) * IN_ + k];
            }
            #pragma unroll
            for (int r = 0; r < 8; r++)
                C[(size_t)(tile * 16 + g + 2 * r) * H_ + c] = acc[r];
        }
    }
}

// ---------------------------------------------------------------------------
// Stage GEMM kernel: for layers li=1..4 with c = s-li valid, compute
//   xpc[li][b][t][j] = dot(W_ih[li-1][j], prev[b, t0+t, :]) + b_ih + b_hh
// 256 CTAs (li-1, b), 256 threads (col jg<128, row parity g). W_ih in smem
// (40 KB, loaded once per CTA); 16-row A tiles staged in smem; f32x2 FMAs.
// Low regs (~60) + 46.4 KB smem -> 4 CTAs/SM possible, all 256 resident.
// ---------------------------------------------------------------------------
__global__ void __launch_bounds__(256)
gs_k(int s, const float* __restrict__ bufA, const float* __restrict__ bufB,
     const float* __restrict__ W_ih, const float* __restrict__ b_ih,
     const float* __restrict__ b_hh, float* __restrict__ xpc)
{
    const int li = (blockIdx.x >> 6) + 1;    // 1..4
    const int b  = blockIdx.x & 63;
    const int c  = s - li;
    if (c < 0 || c >= NC_) return;           // uniform per CTA
    const int t0 = c * TC_;

    __shared__ __align__(16) float Ws[H_ * H_];      // 40000 B
    __shared__ __align__(16) float tile_s[16 * H_];  //  6400 B

    const float* prev = (li & 1) ? bufA : bufB;      // layer li-1 output

    // Load W_ih[li-1] into smem (2500 float4)
    {
        const float4* src = reinterpret_cast<const float4*>(
            W_ih + (size_t)(li - 1) * H_ * H_);
        float4* dst = reinterpret_cast<float4*>(Ws);
        for (int i = threadIdx.x; i < H_ * H_ / 4; i += 256) dst[i] = src[i];
    }

    const int jg = threadIdx.x & 127;
    const int g  = threadIdx.x >> 7;
    const bool act = (jg < H_);
    const float bias = act ? (b_ih[li * H_ + jg] + b_hh[li * H_ + jg]) : 0.0f;

    const float* arow = prev + ((size_t)b * T_ + t0) * H_;
    float* orow = xpc + (size_t)(li * B_ + b) * (TC_ * H_);

    for (int tt = 0; tt < TC_; tt += 16) {
        __syncthreads();   // covers Ws (first iter) + prev tile consumption
        {
            const float4* ts = reinterpret_cast<const float4*>(arow + tt * H_);
            float4* td = reinterpret_cast<float4*>(tile_s);
            for (int i = threadIdx.x; i < 16 * H_ / 4; i += 256) td[i] = ts[i];
        }
        __syncthreads();

        if (act) {
            ull acc[8];
            #pragma unroll
            for (int r = 0; r < 8; r++) acc[r] = 0ull;
            const ulonglong2* Wr = reinterpret_cast<const ulonglong2*>(Ws + jg * H_);
            #pragma unroll 5
            for (int k4 = 0; k4 < 25; k4++) {
                const ulonglong2 wv = Wr[k4];
                #pragma unroll
                for (int r = 0; r < 8; r++) {
                    const ulonglong2 av = *reinterpret_cast<const ulonglong2*>(
                        tile_s + (g + 2 * r) * H_ + 4 * k4);
                    acc[r] = ffma2(wv.x, av.x, acc[r]);
                    acc[r] = ffma2(wv.y, av.y, acc[r]);
                }
            }
            #pragma unroll
            for (int r = 0; r < 8; r++)
                orow[(tt + g + 2 * r) * H_ + jg] = bias + lo2(acc[r]) + hi2(acc[r]);
        }
    }
}

// ---------------------------------------------------------------------------
// Stage scan kernel: 320 CTAs (li, b) x 128 threads; chunk c = s-li.
//   1) copy xp chunk (64x100) to smem (xp0 for li=0, xpc otherwise)
//   2) 64 recurrent steps: thread j owns neuron j, W_hh row in 100 regs,
//      h double-buffered in smem, xpv folded into accumulator init.
// ~120 regs -> 4 CTAs/SM possible; all 320 resident.
// ---------------------------------------------------------------------------
__global__ void __launch_bounds__(128)
ss_k(int s, const float* __restrict__ xp0, const float* __restrict__ xpc,
     float* __restrict__ bufA, float* __restrict__ bufB,
     const float* __restrict__ W_hh, const float* __restrict__ h0all,
     float* __restrict__ hst, float* __restrict__ hfin)
{
    const int li = blockIdx.x >> 6;          // 0..4
    const int b  = blockIdx.x & 63;
    const int c  = s - li;
    if (c < 0 || c >= NC_) return;           // uniform per CTA
    const int t0 = c * TC_;

    __shared__ __align__(16) float xp_s[TC_ * H_];   // 25600 B
    __shared__ __align__(16) float h_s[2][104];      //   832 B

    const int tid = threadIdx.x;
    const int j   = tid;
    const bool act = (j < H_);
    const int jr  = act ? j : 0;

    float* obuf = (li & 1) ? bufB : bufA;            // this layer's output
    float* orow = obuf + ((size_t)b * T_ + t0) * H_;

    // 1) stage xp chunk into smem (1600 float4)
    {
        const float* src = (li == 0)
            ? xp0 + ((size_t)b * T_ + t0) * H_
            : xpc + (size_t)(li * B_ + b) * (TC_ * H_);
        const float4* s4 = reinterpret_cast<const float4*>(src);
        float4* d4 = reinterpret_cast<float4*>(xp_s);
        for (int i = tid; i < TC_ * H_ / 4; i += 128) d4[i] = s4[i];
    }

    // 2) W_hh row in registers + h init
    ulonglong2 whh[25];
    #pragma unroll
    for (int i = 0; i < 25; i++) { whh[i].x = 0ull; whh[i].y = 0ull; }
    if (act) {
        const ulonglong2* wp = reinterpret_cast<const ulonglong2*>(
            W_hh + ((size_t)li * H_ + j) * H_);
        #pragma unroll
        for (int i = 0; i < 25; i++) whh[i] = wp[i];

        h_s[0][j] = (c == 0) ? h0all[((size_t)li * B_ + b) * H_ + j]
                             : hst[((size_t)li * B_ + b) * H_ + j];
    }
    __syncthreads();   // xp_s complete + h_s[0] ready

    int cur = 0;
    float th = 0.0f;

    for (int t = 0; t < TC_; t++) {
        ull a0 = pack2(xp_s[t * H_ + jr], 0.0f);
        ull a1 = 0ull, a2 = 0ull, a3 = 0ull;
        const ulonglong2* h2 = reinterpret_cast<const ulonglong2*>(h_s[cur]);
        #pragma unroll
        for (int i = 0; i < 25; i++) {           // 25 broadcast LDS.128
            const ulonglong2 hv = h2[i];
            if (i & 1) { a2 = ffma2(whh[i].x, hv.x, a2);
                         a3 = ffma2(whh[i].y, hv.y, a3); }
            else       { a0 = ffma2(whh[i].x, hv.x, a0);
                         a1 = ffma2(whh[i].y, hv.y, a1); }
        }
        const ull sall = addf2(addf2(a0, a2), addf2(a1, a3));
        th = fast_tanh(lo2(sall) + hi2(sall));

        if (act) {
            h_s[cur ^ 1][j] = th;
            orow[t * H_ + j] = th;               // layer output to global
        }
        __syncthreads();
        cur ^= 1;
    }

    if (act) {
        hst[((size_t)li * B_ + b) * H_ + j] = th;
        if (c == NC_ - 1) hfin[((size_t)li * B_ + b) * H_ + j] = th;
    }
}

// ---------------------------------------------------------------------------
// Output projection: y[m][o] = sum_k A[m][k]*Wout[o][k] + bout[o]
// ---------------------------------------------------------------------------
__global__ void __launch_bounds__(256)
proj_k(const float* __restrict__ A, const float* __restrict__ Wout,
       const float* __restrict__ bout, float* __restrict__ y)
{
    __shared__ __align__(16) float Ws[OUT_ * H_];
    __shared__ float bs[OUT_];
    __shared__ __align__(16) float As[16 * H_];

    for (int i = threadIdx.x; i < OUT_ * H_; i += 256) Ws[i] = Wout[i];
    if (threadIdx.x < OUT_) bs[threadIdx.x] = bout[threadIdx.x];

    const int o  = threadIdx.x & 15;
    const int mi = threadIdx.x >> 4;

    const int tilesTotal = M_ / 16;
    for (int tile = blockIdx.x; tile < tilesTotal; tile += gridDim.x) {
        __syncthreads();
        const float* Arow = A + (size_t)tile * 16 * H_;
        for (int i = threadIdx.x; i < 16 * H_; i += 256) As[i] = Arow[i];
        __syncthreads();

        if (o < OUT_) {
            float acc = bs[o];
            #pragma unroll 4
            for (int k = 0; k < H_; k++)
                acc += As[mi * H_ + k] * Ws[o * H_ + k];
            y[(size_t)(tile * 16 + mi) * OUT_ + o] = acc;
        }
    }
}

// ---------------------------------------------------------------------------
// kernel_launch: 73 plain default-stream launches (prologue + per stage
// {gemm, scan} + proj). NO streams/events — only proven capture-safe APIs.
// Output: concat( y [B,T,OUT] , h_finals [L,B,H] )
// ---------------------------------------------------------------------------
extern "C" void kernel_launch(void* const* d_in, const int* in_sizes, int n_in,
                              void* d_out, int out_size)
{
    const float* x           = (const float*)d_in[0];
    const float* hidden_prev = (const float*)d_in[1];
    const float* W_ih0       = (const float*)d_in[2];
    const float* W_ih        = (const float*)d_in[3];
    const float* W_hh        = (const float*)d_in[4];
    const float* b_ih        = (const float*)d_in[5];
    const float* b_hh        = (const float*)d_in[6];
    const float* W_out       = (const float*)d_in[7];
    const float* b_out       = (const float*)d_in[8];

    float* out  = (float*)d_out;
    float* y    = out;
    float* hfin = out + (size_t)M_ * OUT_;

    float *bufA, *bufB, *xp0, *xpc, *hstBase;
    cudaGetSymbolAddress((void**)&bufA, g_bufA);
    cudaGetSymbolAddress((void**)&bufB, g_bufB);
    cudaGetSymbolAddress((void**)&xp0,  g_xp0);
    cudaGetSymbolAddress((void**)&xpc,  g_xpc);
    cudaGetSymbolAddress((void**)&hstBase, g_hst);

    // Prologue: layer-0 xp for the whole sequence (depends only on x).
    gemm0_k<<<1024, 256>>>(x, W_ih0, b_ih, b_hh, xp0);

    // Wavefront: per stage, gemm for layers 1..4 then scans for all layers.
    for (int s = 0; s < NSTAGE; s++) {
        if (s >= 1)
            gs_k<<<4 * B_, 256>>>(s, bufA, bufB, W_ih, b_ih, b_hh, xpc);
        ss_k<<<L_ * B_, 128>>>(s, xp0, xpc, bufA, bufB,
                               W_hh, hidden_prev, hstBase, hfin);
    }

    // Layer 4 output lives in bufA.
    proj_k<<<512, 256>>>(bufA, W_out, b_out, y);
}

// round 12
// speedup vs baseline: 1.2572x; 1.2572x over previous
#include <cuda_runtime.h>
#include <cstddef>

using ull = unsigned long long;

// Problem constants
constexpr int B_   = 64;
constexpr int T_   = 2048;
constexpr int H_   = 100;
constexpr int IN_  = 10;
constexpr int OUT_ = 10;
constexpr int L_   = 5;
constexpr int M_   = B_ * T_;          // 131072 rows
constexpr int BUF_ELEMS = M_ * H_;     // 52.4 MB

constexpr int TC_    = 64;             // timesteps per chunk
constexpr int NC_    = T_ / TC_;       // 32 chunks
constexpr int NSTAGE = NC_ + L_ - 1;   // 36 wavefront stages

// Scratch (device globals: no allocation anywhere)
__device__ float g_bufA[BUF_ELEMS];                      // layer-4 outputs (for proj)
__device__ float g_xp0[BUF_ELEMS];                       // precomputed layer-0 xp
__device__ float g_xpc[2 * L_ * B_ * TC_ * H_];          // xp chunks, parity by c&1
__device__ float g_hst[L_ * B_ * H_];                    // hidden-state carry

// ---------------------------------------------------------------------------
// Packed f32x2 helpers (sm_103a FFMA2/FADD2 via PTX)
// ---------------------------------------------------------------------------
__device__ __forceinline__ ull ffma2(ull a, ull b, ull c) {
    ull d;
    asm("fma.rn.f32x2 %0, %1, %2, %3;" : "=l"(d) : "l"(a), "l"(b), "l"(c));
    return d;
}
__device__ __forceinline__ ull addf2(ull a, ull b) {
    ull d;
    asm("add.rn.f32x2 %0, %1, %2;" : "=l"(d) : "l"(a), "l"(b));
    return d;
}
__device__ __forceinline__ ull pack2(float lo, float hi) {
    ull r;
    asm("mov.b64 %0, {%1, %2};" : "=l"(r) : "f"(lo), "f"(hi));
    return r;
}
__device__ __forceinline__ float lo2(ull v) {
    return __uint_as_float((unsigned)(v & 0xFFFFFFFFull));
}
__device__ __forceinline__ float hi2(ull v) {
    return __uint_as_float((unsigned)(v >> 32));
}

// ---------------------------------------------------------------------------
// Fast, overflow-safe tanh: tanh(x) = sign(x)*(1-e)/(1+e), e = 2^(-2|x|log2e)
// ---------------------------------------------------------------------------
__device__ __forceinline__ float fast_tanh(float x) {
    float t = fabsf(x) * -2.8853900817779268f;   // -2*log2(e)*|x|
    float e;
    asm("ex2.approx.f32 %0, %1;" : "=f"(e) : "f"(t));
    float r = __fdividef(1.0f - e, 1.0f + e);
    return copysignf(r, x);
}

// Batched dot over 100 floats: operands smem (broadcast), weights in regs.
// Two load batches (13 + 12 x ulonglong2) issued BEFORE their FMA bursts so
// the LDS pipeline runs ahead of consumption (fixes R11's per-LDS stalls).
__device__ __forceinline__ float dot100(const ulonglong2* __restrict__ hp,
                                        const ulonglong2* __restrict__ w,
                                        ull a0) {
    ull a1 = 0ull, a2 = 0ull, a3 = 0ull;
    ulonglong2 hv[13];
    #pragma unroll
    for (int i = 0; i < 13; i++) hv[i] = hp[i];
    #pragma unroll
    for (int i = 0; i < 13; i++) {
        if (i & 1) { a2 = ffma2(w[i].x, hv[i].x, a2);
                     a3 = ffma2(w[i].y, hv[i].y, a3); }
        else       { a0 = ffma2(w[i].x, hv[i].x, a0);
                     a1 = ffma2(w[i].y, hv[i].y, a1); }
    }
    #pragma unroll
    for (int i = 0; i < 12; i++) hv[i] = hp[13 + i];
    #pragma unroll
    for (int i = 0; i < 12; i++) {
        if (i & 1) { a3 = ffma2(w[13 + i].x, hv[i].x, a3);
                     a2 = ffma2(w[13 + i].y, hv[i].y, a2); }
        else       { a1 = ffma2(w[13 + i].x, hv[i].x, a1);
                     a0 = ffma2(w[13 + i].y, hv[i].y, a0); }
    }
    const ull s = addf2(addf2(a0, a2), addf2(a1, a3));
    return lo2(s) + hi2(s);
}

// ---------------------------------------------------------------------------
// Prologue: layer-0 input GEMM over the ENTIRE sequence (depends only on x).
// ---------------------------------------------------------------------------
__global__ void __launch_bounds__(256)
gemm0_k(const float* __restrict__ A, const float* __restrict__ W,
        const float* __restrict__ b1, const float* __restrict__ b2,
        float* __restrict__ C)
{
    __shared__ __align__(16) float Ws[H_ * IN_];
    __shared__ __align__(16) float As[16 * IN_];

    for (int i = threadIdx.x; i < H_ * IN_; i += 256) Ws[i] = W[i];

    const int c = threadIdx.x & 127;
    const int g = threadIdx.x >> 7;
    const bool act = (c < H_);
    const float bias = act ? (b1[c] + b2[c]) : 0.0f;

    const int tilesTotal = M_ / 16;
    for (int tile = blockIdx.x; tile < tilesTotal; tile += gridDim.x) {
        __syncthreads();
        const float* Arow = A + (size_t)tile * 16 * IN_;
        for (int i = threadIdx.x; i < 16 * IN_; i += 256) As[i] = Arow[i];
        __syncthreads();

        if (act) {
            float acc[8];
            #pragma unroll
            for (int r = 0; r < 8; r++) acc[r] = bias;
            #pragma unroll
            for (int k = 0; k < IN_; k++) {
                const float wv = Ws[c * IN_ + k];
                #pragma unroll
                for (int r = 0; r < 8; r++)
                    acc[r] += wv * As[(g + 2 * r) * IN_ + k];
            }
            #pragma unroll
            for (int r = 0; r < 8; r++)
                C[(size_t)(tile * 16 + g + 2 * r) * H_ + c] = acc[r];
        }
    }
}

// ---------------------------------------------------------------------------
// Fused wavefront stage kernel: 320 CTAs (li,b) x 128 threads; c = s-li.
//  Phase A (scan): copy xp chunk to smem (xp0 if li==0 else xpc[c&1][li][b]),
//    64 recurrent steps; thread j owns neuron j, W_hh row in 100 regs,
//    h double-buffered in smem with BATCHED LDS; h_t overwrites xp_s[t] for
//    the epilogue; layer 4 additionally writes bufA for proj.
//  Phase B (producer gemm, li<4): W_ih[li] row in regs; for each t computes
//    dot(W_ih[li][j], h_t) + biases(li+1) -> xpc[c&1][li+1][b] chunk, i.e.
//    stage s+1's xp. Iterations independent -> fully pipelined, overlaps
//    other CTAs' latency-bound scans on the same SM.
//  Race safety: xpc slot (li+1,b) parity c&1 is written at stage s and read
//    at stage s+1; the stage-s+1 writer (chunk c+1) uses parity (c+1)&1.
//  hst[(li,b)] is touched only by CTA (li,b) across stages.
// ---------------------------------------------------------------------------
__global__ void __launch_bounds__(128, 3)
stage_k(int s, const float* __restrict__ xp0, float* __restrict__ xpc,
        float* __restrict__ bufA,
        const float* __restrict__ W_ih, const float* __restrict__ W_hh,
        const float* __restrict__ b_ih, const float* __restrict__ b_hh,
        const float* __restrict__ h0all, float* __restrict__ hst,
        float* __restrict__ hfin)
{
    const int li = blockIdx.x >> 6;          // 0..4
    const int b  = blockIdx.x & 63;
    const int c  = s - li;
    if (c < 0 || c >= NC_) return;           // uniform per CTA
    const int t0 = c * TC_;
    const int par = c & 1;

    __shared__ __align__(16) float xp_s[TC_ * H_];   // 25600 B
    __shared__ __align__(16) float h_s[2][104];      //   832 B

    const int tid = threadIdx.x;
    const int j   = tid;
    const bool act = (j < H_);
    const int jr  = act ? j : 0;

    // ---- stage xp chunk into smem (1600 float4) ----
    {
        const float* src = (li == 0)
            ? xp0 + ((size_t)b * T_ + t0) * H_
            : xpc + (((size_t)par * L_ + li) * B_ + b) * (TC_ * H_);
        const float4* s4 = reinterpret_cast<const float4*>(src);
        float4* d4 = reinterpret_cast<float4*>(xp_s);
        for (int i = tid; i < TC_ * H_ / 4; i += 128) d4[i] = s4[i];
    }

    // ---- W_hh row in registers + h init ----
    ulonglong2 whh[25];
    #pragma unroll
    for (int i = 0; i < 25; i++) { whh[i].x = 0ull; whh[i].y = 0ull; }
    if (act) {
        const ulonglong2* wp = reinterpret_cast<const ulonglong2*>(
            W_hh + ((size_t)li * H_ + j) * H_);
        #pragma unroll
        for (int i = 0; i < 25; i++) whh[i] = wp[i];

        h_s[0][j] = (c == 0) ? h0all[((size_t)li * B_ + b) * H_ + j]
                             : hst[((size_t)li * B_ + b) * H_ + j];
    }
    __syncthreads();   // xp_s complete + h_s[0] ready

    // ---- Phase A: 64 recurrent steps ----
    float* orow4 = bufA + ((size_t)b * T_ + t0) * H_;   // only used by li==4
    int cur = 0;
    float th = 0.0f;

    for (int t = 0; t < TC_; t++) {
        const ull a0 = pack2(xp_s[t * H_ + jr], 0.0f);
        const float sum = dot100(
            reinterpret_cast<const ulonglong2*>(h_s[cur]), whh, a0);
        th = fast_tanh(sum);

        if (act) {
            h_s[cur ^ 1][j] = th;
            xp_s[t * H_ + j] = th;              // stash h_t for epilogue
            if (li == L_ - 1) orow4[t * H_ + j] = th;
        }
        __syncthreads();
        cur ^= 1;
    }

    if (act) {
        hst[((size_t)li * B_ + b) * H_ + j] = th;
        if (c == NC_ - 1) hfin[((size_t)li * B_ + b) * H_ + j] = th;
    }

    // ---- Phase B: produce xp chunk for layer li+1 (stage s+1) ----
    if (li < L_ - 1) {
        ulonglong2 wih[25];
        #pragma unroll
        for (int i = 0; i < 25; i++) { wih[i].x = 0ull; wih[i].y = 0ull; }
        float bias2 = 0.0f;
        if (act) {
            const ulonglong2* wp = reinterpret_cast<const ulonglong2*>(
                W_ih + ((size_t)li * H_ + j) * H_);   // W_ih[(li+1)-1]
            #pragma unroll
            for (int i = 0; i < 25; i++) wih[i] = wp[i];
            bias2 = b_ih[(li + 1) * H_ + j] + b_hh[(li + 1) * H_ + j];
        }

        float* dst = xpc + (((size_t)par * L_ + (li + 1)) * B_ + b) * (TC_ * H_);

        #pragma unroll 2
        for (int t = 0; t < TC_; t++) {
            const float sum = dot100(
                reinterpret_cast<const ulonglong2*>(xp_s + t * H_), wih, 0ull);
            if (act) dst[t * H_ + j] = bias2 + sum;
        }
    }
}

// ---------------------------------------------------------------------------
// Output projection: y[m][o] = sum_k A[m][k]*Wout[o][k] + bout[o]
// ---------------------------------------------------------------------------
__global__ void __launch_bounds__(256)
proj_k(const float* __restrict__ A, const float* __restrict__ Wout,
       const float* __restrict__ bout, float* __restrict__ y)
{
    __shared__ __align__(16) float Ws[OUT_ * H_];
    __shared__ float bs[OUT_];
    __shared__ __align__(16) float As[16 * H_];

    for (int i = threadIdx.x; i < OUT_ * H_; i += 256) Ws[i] = Wout[i];
    if (threadIdx.x < OUT_) bs[threadIdx.x] = bout[threadIdx.x];

    const int o  = threadIdx.x & 15;
    const int mi = threadIdx.x >> 4;

    const int tilesTotal = M_ / 16;
    for (int tile = blockIdx.x; tile < tilesTotal; tile += gridDim.x) {
        __syncthreads();
        const float* Arow = A + (size_t)tile * 16 * H_;
        for (int i = threadIdx.x; i < 16 * H_; i += 256) As[i] = Arow[i];
        __syncthreads();

        if (o < OUT_) {
            float acc = bs[o];
            #pragma unroll 4
            for (int k = 0; k < H_; k++)
                acc += As[mi * H_ + k] * Ws[o * H_ + k];
            y[(size_t)(tile * 16 + mi) * OUT_ + o] = acc;
        }
    }
}

// ---------------------------------------------------------------------------
// kernel_launch: 38 plain default-stream launches (prologue + 36 fused
// stages + proj). NO streams/events — only proven capture-safe APIs.
// Output: concat( y [B,T,OUT] , h_finals [L,B,H] )
// ---------------------------------------------------------------------------
extern "C" void kernel_launch(void* const* d_in, const int* in_sizes, int n_in,
                              void* d_out, int out_size)
{
    const float* x           = (const float*)d_in[0];
    const float* hidden_prev = (const float*)d_in[1];
    const float* W_ih0       = (const float*)d_in[2];
    const float* W_ih        = (const float*)d_in[3];
    const float* W_hh        = (const float*)d_in[4];
    const float* b_ih        = (const float*)d_in[5];
    const float* b_hh        = (const float*)d_in[6];
    const float* W_out       = (const float*)d_in[7];
    const float* b_out       = (const float*)d_in[8];

    float* out  = (float*)d_out;
    float* y    = out;
    float* hfin = out + (size_t)M_ * OUT_;

    float *bufA, *xp0, *xpc, *hstBase;
    cudaGetSymbolAddress((void**)&bufA, g_bufA);
    cudaGetSymbolAddress((void**)&xp0,  g_xp0);
    cudaGetSymbolAddress((void**)&xpc,  g_xpc);
    cudaGetSymbolAddress((void**)&hstBase, g_hst);

    // Prologue: layer-0 xp for the whole sequence (depends only on x).
    gemm0_k<<<1024, 256>>>(x, W_ih0, b_ih, b_hh, xp0);

    // Wavefront: fused scan + producer-gemm per stage.
    for (int s = 0; s < NSTAGE; s++) {
        stage_k<<<L_ * B_, 128>>>(s, xp0, xpc, bufA,
                                  W_ih, W_hh, b_ih, b_hh,
                                  hidden_prev, hstBase, hfin);
    }

    // Layer-4 outputs live in bufA.
    proj_k<<<512, 256>>>(bufA, W_out, b_out, y);
}

// round 13
// speedup vs baseline: 1.2844x; 1.0216x over previous
#include <cuda_runtime.h>
#include <cstddef>

using ull = unsigned long long;

// Problem constants
constexpr int B_   = 64;
constexpr int T_   = 2048;
constexpr int H_   = 100;
constexpr int IN_  = 10;
constexpr int OUT_ = 10;
constexpr int L_   = 5;
constexpr int M_   = B_ * T_;          // 131072 rows
constexpr int BUF_ELEMS = M_ * H_;     // 52.4 MB

constexpr int TC_  = 64;               // timesteps per chunk
constexpr int NC_  = T_ / TC_;         // 32 chunks

// Scratch (device globals: no allocation anywhere)
__device__ float g_bufA[BUF_ELEMS];                  // layer-4 outputs (for proj)
__device__ float g_xp0[BUF_ELEMS];                   // precomputed layer-0 xp
__device__ float g_xpc[2 * L_ * B_ * TC_ * H_];      // xp chunks, parity by c&1
__device__ int   g_prodF[L_ * B_];                   // xp chunks produced for layer li
__device__ int   g_consF[L_ * B_];                   // xp chunks consumed by layer li

// ---------------------------------------------------------------------------
// Packed f32x2 helpers (sm_103a FFMA2/FADD2 via PTX)
// ---------------------------------------------------------------------------
__device__ __forceinline__ ull ffma2(ull a, ull b, ull c) {
    ull d;
    asm("fma.rn.f32x2 %0, %1, %2, %3;" : "=l"(d) : "l"(a), "l"(b), "l"(c));
    return d;
}
__device__ __forceinline__ ull addf2(ull a, ull b) {
    ull d;
    asm("add.rn.f32x2 %0, %1, %2;" : "=l"(d) : "l"(a), "l"(b));
    return d;
}
__device__ __forceinline__ ull pack2(float lo, float hi) {
    ull r;
    asm("mov.b64 %0, {%1, %2};" : "=l"(r) : "f"(lo), "f"(hi));
    return r;
}
__device__ __forceinline__ float lo2(ull v) {
    return __uint_as_float((unsigned)(v & 0xFFFFFFFFull));
}
__device__ __forceinline__ float hi2(ull v) {
    return __uint_as_float((unsigned)(v >> 32));
}

// ---------------------------------------------------------------------------
// Fast, overflow-safe tanh: tanh(x) = sign(x)*(1-e)/(1+e), e = 2^(-2|x|log2e)
// ---------------------------------------------------------------------------
__device__ __forceinline__ float fast_tanh(float x) {
    float t = fabsf(x) * -2.8853900817779268f;   // -2*log2(e)*|x|
    float e;
    asm("ex2.approx.f32 %0, %1;" : "=f"(e) : "f"(t));
    float r = __fdividef(1.0f - e, 1.0f + e);
    return copysignf(r, x);
}

// Batched dot over 100 floats: operands smem (broadcast-friendly), weights in
// regs. Loads batched ahead of the FMA bursts so the LDS pipeline runs ahead.
__device__ __forceinline__ float dot100(const ulonglong2* __restrict__ hp,
                                        const ulonglong2* __restrict__ w,
                                        ull a0) {
    ull a1 = 0ull, a2 = 0ull, a3 = 0ull;
    ulonglong2 hv[13];
    #pragma unroll
    for (int i = 0; i < 13; i++) hv[i] = hp[i];
    #pragma unroll
    for (int i = 0; i < 13; i++) {
        if (i & 1) { a2 = ffma2(w[i].x, hv[i].x, a2);
                     a3 = ffma2(w[i].y, hv[i].y, a3); }
        else       { a0 = ffma2(w[i].x, hv[i].x, a0);
                     a1 = ffma2(w[i].y, hv[i].y, a1); }
    }
    #pragma unroll
    for (int i = 0; i < 12; i++) hv[i] = hp[13 + i];
    #pragma unroll
    for (int i = 0; i < 12; i++) {
        if (i & 1) { a3 = ffma2(w[13 + i].x, hv[i].x, a3);
                     a2 = ffma2(w[13 + i].y, hv[i].y, a2); }
        else       { a1 = ffma2(w[13 + i].x, hv[i].x, a1);
                     a0 = ffma2(w[13 + i].y, hv[i].y, a0); }
    }
    const ull s = addf2(addf2(a0, a2), addf2(a1, a3));
    return lo2(s) + hi2(s);
}

// ---------------------------------------------------------------------------
// Init: zero the pipeline flags (runs at the head of every replay).
// ---------------------------------------------------------------------------
__global__ void init_k()
{
    const int i = threadIdx.x;
    if (i < L_ * B_) { g_prodF[i] = 0; g_consF[i] = 0; }
}

// ---------------------------------------------------------------------------
// Prologue: layer-0 input GEMM over the ENTIRE sequence (depends only on x).
// ---------------------------------------------------------------------------
__global__ void __launch_bounds__(256)
gemm0_k(const float* __restrict__ A, const float* __restrict__ W,
        const float* __restrict__ b1, const float* __restrict__ b2,
        float* __restrict__ C)
{
    __shared__ __align__(16) float Ws[H_ * IN_];
    __shared__ __align__(16) float As[16 * IN_];

    for (int i = threadIdx.x; i < H_ * IN_; i += 256) Ws[i] = W[i];

    const int c = threadIdx.x & 127;
    const int g = threadIdx.x >> 7;
    const bool act = (c < H_);
    const float bias = act ? (b1[c] + b2[c]) : 0.0f;

    const int tilesTotal = M_ / 16;
    for (int tile = blockIdx.x; tile < tilesTotal; tile += gridDim.x) {
        __syncthreads();
        const float* Arow = A + (size_t)tile * 16 * IN_;
        for (int i = threadIdx.x; i < 16 * IN_; i += 256) As[i] = Arow[i];
        __syncthreads();

        if (act) {
            float acc[8];
            #pragma unroll
            for (int r = 0; r < 8; r++) acc[r] = bias;
            #pragma unroll
            for (int k = 0; k < IN_; k++) {
                const float wv = Ws[c * IN_ + k];
                #pragma unroll
                for (int r = 0; r < 8; r++)
                    acc[r] += wv * As[(g + 2 * r) * IN_ + k];
            }
            #pragma unroll
            for (int r = 0; r < 8; r++)
                C[(size_t)(tile * 16 + g + 2 * r) * H_ + c] = acc[r];
        }
    }
}

// ---------------------------------------------------------------------------
// Persistent pipeline kernel: 320 CTAs (li = bid>>6, b = bid&63), each owns
// (layer li, batch b) for ALL 32 chunks. Per chunk c:
//   acquire xp (li==0: from xp0; li>=1: wait prodF >= c+1, copy xpc slot c&1,
//   release consF = c+1), reload W_hh row (L2-hot), run 64 recurrent steps
//   (h_s persists across chunks; layer 4 also writes bufA), then (li<4)
//   backpressure-wait consF[li+1] >= c-1, produce layer li+1's chunk-c xp
//   with W_ih row in regs, release prodF[li+1] = c+1.
// Residency: __launch_bounds__(128,3) + 26.5 KB smem -> >=3 CTAs/SM = 444
// slots >= 320 -> full wave-1 placement, pipeline cannot deadlock (deps form
// a bounded-buffer DAG with strictly decreasing chunk indices).
// ---------------------------------------------------------------------------
__global__ void __launch_bounds__(128, 3)
persist_k(const float* __restrict__ xp0, float* __restrict__ xpc,
          float* __restrict__ bufA,
          const float* __restrict__ W_ih, const float* __restrict__ W_hh,
          const float* __restrict__ b_ih, const float* __restrict__ b_hh,
          const float* __restrict__ h0all, float* __restrict__ hfin)
{
    const int li = blockIdx.x >> 6;          // 0..4
    const int b  = blockIdx.x & 63;

    __shared__ __align__(16) float xp_s[TC_ * H_];   // 25600 B
    __shared__ __align__(16) float h_s[2][104];      //   832 B

    const int tid = threadIdx.x;
    const int j   = tid;
    const bool act = (j < H_);
    const int jr  = act ? j : 0;

    volatile int* prodF = (volatile int*)g_prodF;
    volatile int* consF = (volatile int*)g_consF;

    // h init (once; h_s persists across chunks)
    if (act) h_s[0][j] = h0all[((size_t)li * B_ + b) * H_ + j];

    float bias2 = 0.0f;
    if (li < L_ - 1 && act)
        bias2 = b_ih[(li + 1) * H_ + j] + b_hh[(li + 1) * H_ + j];

    for (int c = 0; c < NC_; c++) {
        const int t0  = c * TC_;
        const int par = c & 1;

        // ---- acquire + copy xp chunk into smem ----
        if (li > 0) {
            if (tid == 0) {
                while (prodF[li * B_ + b] < c + 1) __nanosleep(64);
            }
            __syncthreads();
            __threadfence();
        }
        {
            const float* src = (li == 0)
                ? xp0 + ((size_t)b * T_ + t0) * H_
                : xpc + (((size_t)par * L_ + li) * B_ + b) * (TC_ * H_);
            const float4* s4 = reinterpret_cast<const float4*>(src);
            float4* d4 = reinterpret_cast<float4*>(xp_s);
            for (int i = tid; i < TC_ * H_ / 4; i += 128) d4[i] = s4[i];
        }
        __syncthreads();
        if (li > 0 && tid == 0) {
            __threadfence();
            atomicExch(&g_consF[li * B_ + b], c + 1);
        }

        // ---- W_hh row (reloaded per chunk; L2-hot; keeps live ranges
        //      disjoint from wih so regs stay under the 168 cap) ----
        ulonglong2 whh[25];
        #pragma unroll
        for (int i = 0; i < 25; i++) { whh[i].x = 0ull; whh[i].y = 0ull; }
        if (act) {
            const ulonglong2* wp = reinterpret_cast<const ulonglong2*>(
                W_hh + ((size_t)li * H_ + j) * H_);
            #pragma unroll
            for (int i = 0; i < 25; i++) whh[i] = wp[i];
        }
        __syncthreads();   // xp_s ready for all; h_s ready

        // ---- 64 recurrent steps ----
        float* orow4 = bufA + ((size_t)b * T_ + t0) * H_;  // used by li==4
        int cur = 0;
        float th = 0.0f;

        for (int t = 0; t < TC_; t++) {
            const ull a0 = pack2(xp_s[t * H_ + jr], 0.0f);
            const float sum = dot100(
                reinterpret_cast<const ulonglong2*>(h_s[cur]), whh, a0);
            th = fast_tanh(sum);

            if (act) {
                h_s[cur ^ 1][j] = th;
                xp_s[t * H_ + j] = th;                // stash h_t for phase B
                if (li == L_ - 1) orow4[t * H_ + j] = th;
            }
            __syncthreads();
            cur ^= 1;
        }

        if (act && c == NC_ - 1)
            hfin[((size_t)li * B_ + b) * H_ + j] = th;

        // ---- phase B: produce xp chunk c for layer li+1 ----
        if (li < L_ - 1) {
            // backpressure: slot par was last read by consumer chunk c-2
            if (c >= 2) {
                if (tid == 0) {
                    while (consF[(li + 1) * B_ + b] < c - 1) __nanosleep(64);
                }
                __syncthreads();
                __threadfence();
            }

            ulonglong2 wih[25];
            #pragma unroll
            for (int i = 0; i < 25; i++) { wih[i].x = 0ull; wih[i].y = 0ull; }
            if (act) {
                const ulonglong2* wp = reinterpret_cast<const ulonglong2*>(
                    W_ih + ((size_t)li * H_ + j) * H_);   // W_ih[(li+1)-1]
                #pragma unroll
                for (int i = 0; i < 25; i++) wih[i] = wp[i];
            }

            float* dst = xpc +
                (((size_t)par * L_ + (li + 1)) * B_ + b) * (TC_ * H_);

            #pragma unroll 2
            for (int t = 0; t < TC_; t++) {
                const float sum = dot100(
                    reinterpret_cast<const ulonglong2*>(xp_s + t * H_),
                    wih, 0ull);
                if (act) dst[t * H_ + j] = bias2 + sum;
            }

            __syncthreads();
            if (tid == 0) {
                __threadfence();
                atomicExch(&g_prodF[(li + 1) * B_ + b], c + 1);
            }
        }
    }
}

// ---------------------------------------------------------------------------
// Output projection: y[m][o] = sum_k A[m][k]*Wout[o][k] + bout[o]
// ---------------------------------------------------------------------------
__global__ void __launch_bounds__(256)
proj_k(const float* __restrict__ A, const float* __restrict__ Wout,
       const float* __restrict__ bout, float* __restrict__ y)
{
    __shared__ __align__(16) float Ws[OUT_ * H_];
    __shared__ float bs[OUT_];
    __shared__ __align__(16) float As[16 * H_];

    for (int i = threadIdx.x; i < OUT_ * H_; i += 256) Ws[i] = Wout[i];
    if (threadIdx.x < OUT_) bs[threadIdx.x] = bout[threadIdx.x];

    const int o  = threadIdx.x & 15;
    const int mi = threadIdx.x >> 4;

    const int tilesTotal = M_ / 16;
    for (int tile = blockIdx.x; tile < tilesTotal; tile += gridDim.x) {
        __syncthreads();
        const float* Arow = A + (size_t)tile * 16 * H_;
        for (int i = threadIdx.x; i < 16 * H_; i += 256) As[i] = Arow[i];
        __syncthreads();

        if (o < OUT_) {
            float acc = bs[o];
            #pragma unroll 4
            for (int k = 0; k < H_; k++)
                acc += As[mi * H_ + k] * Ws[o * H_ + k];
            y[(size_t)(tile * 16 + mi) * OUT_ + o] = acc;
        }
    }
}

// ---------------------------------------------------------------------------
// kernel_launch: 4 plain default-stream launches (init flags, layer-0 gemm,
// persistent pipeline, projection). NO streams/events — capture-safe APIs
// only. Output: concat( y [B,T,OUT] , h_finals [L,B,H] )
// ---------------------------------------------------------------------------
extern "C" void kernel_launch(void* const* d_in, const int* in_sizes, int n_in,
                              void* d_out, int out_size)
{
    const float* x           = (const float*)d_in[0];
    const float* hidden_prev = (const float*)d_in[1];
    const float* W_ih0       = (const float*)d_in[2];
    const float* W_ih        = (const float*)d_in[3];
    const float* W_hh        = (const float*)d_in[4];
    const float* b_ih        = (const float*)d_in[5];
    const float* b_hh        = (const float*)d_in[6];
    const float* W_out       = (const float*)d_in[7];
    const float* b_out       = (const float*)d_in[8];

    float* out  = (float*)d_out;
    float* y    = out;
    float* hfin = out + (size_t)M_ * OUT_;

    float *bufA, *xp0, *xpc;
    cudaGetSymbolAddress((void**)&bufA, g_bufA);
    cudaGetSymbolAddress((void**)&xp0,  g_xp0);
    cudaGetSymbolAddress((void**)&xpc,  g_xpc);

    // Zero pipeline flags (fresh for every replay).
    init_k<<<1, 512>>>();

    // Layer-0 xp for the whole sequence (depends only on x).
    gemm0_k<<<1024, 256>>>(x, W_ih0, b_ih, b_hh, xp0);

    // Persistent wavefront pipeline: all layers, all chunks, one launch.
    persist_k<<<L_ * B_, 128>>>(xp0, xpc, bufA,
                                W_ih, W_hh, b_ih, b_hh,
                                hidden_prev, hfin);

    // Layer-4 outputs live in bufA.
    proj_k<<<512, 256>>>(bufA, W_out, b_out, y);
}